// round 3
// baseline (speedup 1.0000x reference)
#include <cuda_runtime.h>
#include <cuda_bf16.h>
#include <cstdint>
#include <cstddef>

#define BATCH   2
#define SEQ     4096
#define DMODEL  2048
#define DINNER  4096
#define NHEADS  32
#define DHEAD   128
#define DSTATE  64
#define CONVDIM 4224          // DINNER + 2*DSTATE
#define EPROJ   8352          // 2*DINNER + 2*DSTATE + NHEADS
#define NCHUNK  16
#define CHUNK   256
#define MROWS   8192          // BATCH*SEQ

// ---------------- device scratch (static: allocation-free) ----------------
__device__ float g_zx[(size_t)MROWS * EPROJ];     // in_proj output
__device__ float g_xc[(size_t)MROWS * CONVDIM];   // conv+silu output
__device__ float g_dtv[(size_t)MROWS * NHEADS];   // softplus dt
__device__ float g_cum[BATCH * NCHUNK * NHEADS * CHUNK]; // per-chunk cumsum(dA)
__device__ float g_st[(size_t)BATCH * NCHUNK * NHEADS * DHEAD * DSTATE]; // chunk states
__device__ float g_pv[(size_t)BATCH * NCHUNK * NHEADS * DHEAD * DSTATE]; // prev states
__device__ float g_y [(size_t)MROWS * DINNER];    // y, then yn in place

// ---------------- NT SGEMM: C[M,N] = A[M,K] * B[N,K]^T (all row-major, K contig)
__global__ __launch_bounds__(256, 2)
void sgemm_nt(const float* __restrict__ A, const float* __restrict__ B,
              float* __restrict__ C, int M, int N, int K) {
    __shared__ float As[16][128];
    __shared__ float Bs[16][128];
    const int tid = threadIdx.x;
    const int m0 = blockIdx.y * 128, n0 = blockIdx.x * 128;
    const int lr = tid >> 2;             // 0..63
    const int lc = (tid & 3) << 2;       // 0,4,8,12
    const int ty = tid >> 4, tx = tid & 15;
    float acc[8][8];
    #pragma unroll
    for (int i = 0; i < 8; i++)
        #pragma unroll
        for (int j = 0; j < 8; j++) acc[i][j] = 0.f;

    for (int k0 = 0; k0 < K; k0 += 16) {
        #pragma unroll
        for (int r = 0; r < 128; r += 64) {
            int row = lr + r;
            float4 v = *(const float4*)&A[(size_t)(m0 + row) * K + k0 + lc];
            As[lc + 0][row] = v.x; As[lc + 1][row] = v.y;
            As[lc + 2][row] = v.z; As[lc + 3][row] = v.w;
        }
        #pragma unroll
        for (int r = 0; r < 128; r += 64) {
            int row = lr + r;
            float4 v = make_float4(0.f, 0.f, 0.f, 0.f);
            if (n0 + row < N)
                v = *(const float4*)&B[(size_t)(n0 + row) * K + k0 + lc];
            Bs[lc + 0][row] = v.x; Bs[lc + 1][row] = v.y;
            Bs[lc + 2][row] = v.z; Bs[lc + 3][row] = v.w;
        }
        __syncthreads();
        #pragma unroll
        for (int kk = 0; kk < 16; kk++) {
            float a[8], b[8];
            *(float4*)&a[0] = *(const float4*)&As[kk][ty * 8];
            *(float4*)&a[4] = *(const float4*)&As[kk][ty * 8 + 4];
            *(float4*)&b[0] = *(const float4*)&Bs[kk][tx * 8];
            *(float4*)&b[4] = *(const float4*)&Bs[kk][tx * 8 + 4];
            #pragma unroll
            for (int i = 0; i < 8; i++)
                #pragma unroll
                for (int j = 0; j < 8; j++)
                    acc[i][j] += a[i] * b[j];
        }
        __syncthreads();
    }
    #pragma unroll
    for (int i = 0; i < 8; i++) {
        int m = m0 + ty * 8 + i;
        #pragma unroll
        for (int j = 0; j < 8; j += 4) {
            int n = n0 + tx * 8 + j;
            if (n < N)
                *(float4*)&C[(size_t)m * N + n] =
                    make_float4(acc[i][j], acc[i][j+1], acc[i][j+2], acc[i][j+3]);
        }
    }
}

// ---------------- conv1d (depthwise, causal, D_CONV=4) + SiLU ----------------
__global__ void conv_silu_k(const float* __restrict__ cw, const float* __restrict__ cb) {
    size_t idx = (size_t)blockIdx.x * 256 + threadIdx.x;
    int c = (int)(idx % CONVDIM);
    size_t bl = idx / CONVDIM;
    int l = (int)(bl % SEQ);
    int b = (int)(bl / SEQ);
    float acc = cb[c];
    #pragma unroll
    for (int k = 0; k < 4; k++) {
        int ls = l - 3 + k;
        if (ls >= 0)
            acc += g_zx[((size_t)(b * SEQ + ls)) * EPROJ + DINNER + c] * cw[c * 4 + k];
    }
    acc = acc / (1.f + expf(-acc));
    g_xc[idx] = acc;
}

// ---------------- dt softplus + per-chunk cumsum(dA) ----------------
__global__ void dtcum_k(const float* __restrict__ dtb, const float* __restrict__ Alog) {
    int blk = blockIdx.x;                // ((b*16+c)*32+h)
    int h = blk & 31, c = (blk >> 5) & 15, b = blk >> 9;
    int s = threadIdx.x;
    int l = c * CHUNK + s;
    float raw = g_zx[((size_t)(b * SEQ + l)) * EPROJ + (EPROJ - NHEADS) + h] + dtb[h];
    float dtv = (raw > 20.f) ? raw : log1pf(expf(raw));
    g_dtv[(size_t)(b * SEQ + l) * NHEADS + h] = dtv;
    float dA = dtv * (-expf(Alog[h]));
    __shared__ float sc[256];
    sc[s] = dA;
    __syncthreads();
    for (int off = 1; off < 256; off <<= 1) {
        float v = (s >= off) ? sc[s - off] : 0.f;
        __syncthreads();
        sc[s] += v;
        __syncthreads();
    }
    g_cum[blk * CHUNK + s] = sc[s];
}

// ---------------- per-chunk states: st[p,n] = sum_z exp(cumL-cum[z])*dt[z]*x[z,p]*B[z,n]
__global__ __launch_bounds__(256)
void states_k() {
    extern __shared__ float sm[];
    float* xw  = sm;                 // 64*128
    float* Bsh = xw + 64 * 128;      // 64*64
    float* ws  = Bsh + 64 * 64;      // 256
    int blk = blockIdx.x;
    int h = blk & 31, c = (blk >> 5) & 15, b = blk >> 9;
    int t = threadIdx.x;
    float clast = g_cum[blk * CHUNK + 255];
    {
        float cz = g_cum[blk * CHUNK + t];
        float dtv = g_dtv[(size_t)(b * SEQ + c * CHUNK + t) * NHEADS + h];
        ws[t] = expf(clast - cz) * dtv;
    }
    __syncthreads();
    int tx = t & 15, ty = t >> 4;
    int p0 = tx * 8, n0 = ty * 4;
    float acc[8][4];
    #pragma unroll
    for (int i = 0; i < 8; i++)
        #pragma unroll
        for (int j = 0; j < 4; j++) acc[i][j] = 0.f;
    size_t base = (size_t)(b * SEQ + c * CHUNK) * CONVDIM;
    for (int zt = 0; zt < 4; zt++) {
        #pragma unroll
        for (int i = 0; i < 32; i++) {
            int lin = t + i * 256; int zz = lin >> 7; int p = lin & 127; int z = zt * 64 + zz;
            xw[zz * 128 + p] = g_xc[base + (size_t)z * CONVDIM + h * DHEAD + p] * ws[z];
        }
        #pragma unroll
        for (int i = 0; i < 16; i++) {
            int lin = t + i * 256; int zz = lin >> 6; int n = lin & 63; int z = zt * 64 + zz;
            Bsh[zz * 64 + n] = g_xc[base + (size_t)z * CONVDIM + DINNER + n];
        }
        __syncthreads();
        #pragma unroll
        for (int zz = 0; zz < 64; zz++) {
            float xv[8];
            *(float4*)&xv[0] = *(const float4*)&xw[zz * 128 + p0];
            *(float4*)&xv[4] = *(const float4*)&xw[zz * 128 + p0 + 4];
            float4 bv = *(const float4*)&Bsh[zz * 64 + n0];
            float bb[4] = {bv.x, bv.y, bv.z, bv.w};
            #pragma unroll
            for (int i = 0; i < 8; i++)
                #pragma unroll
                for (int j = 0; j < 4; j++)
                    acc[i][j] += xv[i] * bb[j];
        }
        __syncthreads();
    }
    size_t ob = (size_t)blk * DHEAD * DSTATE;
    #pragma unroll
    for (int i = 0; i < 8; i++)
        #pragma unroll
        for (int j = 0; j < 4; j++)
            g_st[ob + (size_t)(p0 + i) * DSTATE + n0 + j] = acc[i][j];
}

// ---------------- inter-chunk scan (16 steps, parallel over (b,h) and (p,n))
__global__ void scan_k() {
    int blk = blockIdx.x;                // b*32 + h
    int h = blk & 31, b = blk >> 5;
    int t = threadIdx.x;
    float carry[32];
    #pragma unroll
    for (int k = 0; k < 32; k++) carry[k] = 0.f;
    for (int c = 0; c < NCHUNK; c++) {
        int idx = (b * NCHUNK + c) * NHEADS + h;
        float decay = expf(g_cum[idx * CHUNK + 255]);
        size_t base = (size_t)idx * DHEAD * DSTATE;
        #pragma unroll
        for (int k = 0; k < 32; k++) {
            size_t e = base + t + k * 256;
            g_pv[e] = carry[k];
            carry[k] = carry[k] * decay + g_st[e];
        }
    }
}

// ---------------- Y kernel: Y = masked(C B^T L) @ xdt + exp(cum)*C@prev^T + D*x
#define BTS 260
#define CTS 68
#define PTS 132
__global__ __launch_bounds__(256, 1)
void y_k(const float* __restrict__ Dvec) {
    extern __shared__ float sm[];
    float* Bt   = sm;                  // [64][BTS]  B^T (n-major)
    float* Gtt  = Bt + 64 * BTS;       // [256][64]  G^T (z-major, masked*L)
    float* Ct   = Gtt + 256 * 64;      // [64][CTS]  C^T tile (n-major)
    float* sX   = Ct + 64 * CTS;       // [64][128]  xdt z-tile
    float* pT   = sX + 64 * 128;       // [64][PTS]  prev^T (n-major)
    float* cums = pT + 64 * PTS;       // [256]
    float* sdt  = cums + 256;          // [256]
    int blk = blockIdx.x;
    int h = blk & 31, c = (blk >> 5) & 15, b = blk >> 9;
    int t = threadIdx.x;
    size_t base = (size_t)(b * SEQ + c * CHUNK) * CONVDIM;

    cums[t] = g_cum[blk * CHUNK + t];
    sdt[t]  = g_dtv[(size_t)(b * SEQ + c * CHUNK + t) * NHEADS + h];
    #pragma unroll
    for (int i = 0; i < 64; i++) {
        int lin = t + i * 256; int n = lin & 63; int z = lin >> 6;
        Bt[n * BTS + z] = g_xc[base + (size_t)z * CONVDIM + DINNER + n];
    }
    size_t pvb = (size_t)blk * DHEAD * DSTATE;
    #pragma unroll
    for (int i = 0; i < 32; i++) {
        int lin = t + i * 256; int n = lin & 63; int p = lin >> 6;
        pT[n * PTS + p] = g_pv[pvb + (size_t)p * DSTATE + n];
    }
    __syncthreads();
    float Dh = Dvec[h];
    const int sg = t & 15, zg = t >> 4;    // phase-1 mapping
    const int pg = t & 15, sg2 = t >> 4;   // phase-2/3 mapping

    for (int st = 0; st < 4; st++) {
        int s0 = st * 64;
        #pragma unroll
        for (int i = 0; i < 16; i++) {
            int lin = t + i * 256; int n = lin & 63; int si = lin >> 6;
            Ct[n * CTS + si] = g_xc[base + (size_t)(s0 + si) * CONVDIM + DINNER + DSTATE + n];
        }
        __syncthreads();
        // -------- phase 1: G^T tile = (C_tile · B^T), masked * L --------
        {
            int sl0 = sg * 4, z0 = zg * 16;
            float acc1[4][16];
            #pragma unroll
            for (int i = 0; i < 4; i++)
                #pragma unroll
                for (int j = 0; j < 16; j++) acc1[i][j] = 0.f;
            if (z0 <= s0 + 63) {
                for (int n = 0; n < 64; n++) {
                    float cv[4];
                    *(float4*)cv = *(const float4*)&Ct[n * CTS + sl0];
                    float bz[16];
                    #pragma unroll
                    for (int j = 0; j < 16; j += 4)
                        *(float4*)&bz[j] = *(const float4*)&Bt[n * BTS + z0 + j];
                    #pragma unroll
                    for (int i = 0; i < 4; i++)
                        #pragma unroll
                        for (int j = 0; j < 16; j++)
                            acc1[i][j] += cv[i] * bz[j];
                }
            }
            #pragma unroll
            for (int i = 0; i < 4; i++) {
                int sgl = s0 + sl0 + i;
                float cs = cums[sgl];
                #pragma unroll
                for (int j = 0; j < 16; j++) {
                    int z = z0 + j;
                    float v = (z <= sgl) ? acc1[i][j] * expf(cs - cums[z]) : 0.f;
                    Gtt[z * 64 + sl0 + i] = v;
                }
            }
        }
        __syncthreads();
        // -------- phase 2: Y_tile += G^T-masked @ xdt (skip fully-masked z-tiles)
        int p0 = pg * 8, sl0 = sg2 * 4;
        float acc2[4][8];
        #pragma unroll
        for (int i = 0; i < 4; i++)
            #pragma unroll
            for (int j = 0; j < 8; j++) acc2[i][j] = 0.f;
        for (int zt = 0; zt <= st; zt++) {
            #pragma unroll
            for (int i = 0; i < 32; i++) {
                int lin = t + i * 256; int zz = lin >> 7; int p = lin & 127; int z = zt * 64 + zz;
                sX[zz * 128 + p] = g_xc[base + (size_t)z * CONVDIM + h * DHEAD + p] * sdt[z];
            }
            __syncthreads();
            #pragma unroll
            for (int zz = 0; zz < 64; zz++) {
                float gv[4];
                *(float4*)gv = *(const float4*)&Gtt[(zt * 64 + zz) * 64 + sl0];
                float xv[8];
                *(float4*)&xv[0] = *(const float4*)&sX[zz * 128 + p0];
                *(float4*)&xv[4] = *(const float4*)&sX[zz * 128 + p0 + 4];
                #pragma unroll
                for (int i = 0; i < 4; i++)
                    #pragma unroll
                    for (int j = 0; j < 8; j++)
                        acc2[i][j] += gv[i] * xv[j];
            }
            __syncthreads();
        }
        // -------- phase 3: Y_off = exp(cum[s]) * C · prev^T --------
        {
            float es[4];
            #pragma unroll
            for (int i = 0; i < 4; i++) es[i] = expf(cums[s0 + sl0 + i]);
            for (int n = 0; n < 64; n++) {
                float cv[4];
                *(float4*)cv = *(const float4*)&Ct[n * CTS + sl0];
                float pv[8];
                *(float4*)&pv[0] = *(const float4*)&pT[n * PTS + p0];
                *(float4*)&pv[4] = *(const float4*)&pT[n * PTS + p0 + 4];
                #pragma unroll
                for (int i = 0; i < 4; i++) {
                    float cvs = cv[i] * es[i];
                    #pragma unroll
                    for (int j = 0; j < 8; j++)
                        acc2[i][j] += cvs * pv[j];
                }
            }
        }
        // -------- store: + D*x --------
        #pragma unroll
        for (int i = 0; i < 4; i++) {
            int s = s0 + sl0 + i;
            size_t row = (size_t)(b * SEQ + c * CHUNK + s);
            #pragma unroll
            for (int j = 0; j < 8; j++) {
                int p = p0 + j;
                g_y[row * DINNER + h * DHEAD + p] =
                    acc2[i][j] + Dh * g_xc[row * CONVDIM + h * DHEAD + p];
            }
        }
        __syncthreads();
    }
}

// ---------------- gated RMSNorm (in place on g_y) ----------------
__global__ void gatenorm_k(const float* __restrict__ nw) {
    int row = blockIdx.x;
    __shared__ float yg[DINNER];
    __shared__ float red[256];
    int t = threadIdx.x;
    float ss = 0.f;
    size_t zb = (size_t)row * EPROJ;
    size_t yb = (size_t)row * DINNER;
    #pragma unroll
    for (int i = 0; i < 16; i++) {
        int e = t + i * 256;
        float z = g_zx[zb + e];
        float sz = z / (1.f + expf(-z));
        float v = g_y[yb + e] * sz;
        yg[e] = v;
        ss += v * v;
    }
    red[t] = ss;
    __syncthreads();
    for (int off = 128; off > 0; off >>= 1) {
        if (t < off) red[t] += red[t + off];
        __syncthreads();
    }
    float scale = rsqrtf(red[0] / (float)DINNER + 1e-5f);
    #pragma unroll
    for (int i = 0; i < 16; i++) {
        int e = t + i * 256;
        g_y[yb + e] = yg[e] * scale * nw[e];
    }
}

// ---------------- launch ----------------
extern "C" void kernel_launch(void* const* d_in, const int* in_sizes, int n_in,
                              void* d_out, int out_size) {
    const float* u     = (const float*)d_in[0];
    const float* W_in  = (const float*)d_in[1];
    const float* convw = (const float*)d_in[2];
    const float* convb = (const float*)d_in[3];
    const float* dtb   = (const float*)d_in[4];
    const float* Alog  = (const float*)d_in[5];
    const float* Dvec  = (const float*)d_in[6];
    const float* nw    = (const float*)d_in[7];
    const float* W_out = (const float*)d_in[8];
    float* out = (float*)d_out;

    float *zx_p, *y_p;
    cudaGetSymbolAddress((void**)&zx_p, g_zx);
    cudaGetSymbolAddress((void**)&y_p,  g_y);

    const int STATES_SMEM = (64 * 128 + 64 * 64 + 256) * 4;
    const int Y_SMEM = (64 * BTS + 256 * 64 + 64 * CTS + 64 * 128 + 64 * PTS + 512) * 4;
    cudaFuncSetAttribute(states_k, cudaFuncAttributeMaxDynamicSharedMemorySize, STATES_SMEM);
    cudaFuncSetAttribute(y_k,      cudaFuncAttributeMaxDynamicSharedMemorySize, Y_SMEM);

    // 1. in_proj GEMM: [8192,8352] = u[8192,2048] @ W_in[8352,2048]^T
    sgemm_nt<<<dim3(66, 64), 256>>>(u, W_in, zx_p, MROWS, EPROJ, DMODEL);
    // 2. causal depthwise conv + SiLU
    conv_silu_k<<<(int)(((size_t)MROWS * CONVDIM) / 256), 256>>>(convw, convb);
    // 3. dt softplus + per-chunk cumsum(dA)
    dtcum_k<<<1024, 256>>>(dtb, Alog);
    // 4. per-chunk states
    states_k<<<1024, 256, STATES_SMEM>>>();
    // 5. inter-chunk scan
    scan_k<<<64, 256>>>();
    // 6. Y = diag + off + D*x
    y_k<<<1024, 256, Y_SMEM>>>(Dvec);
    // 7. gated RMSNorm
    gatenorm_k<<<MROWS, 256>>>(nw);
    // 8. out_proj GEMM: [8192,2048] = yn[8192,4096] @ W_out[2048,4096]^T
    sgemm_nt<<<dim3(16, 64), 256>>>(y_p, W_out, out, MROWS, DMODEL, DINNER);
}

// round 6
// speedup vs baseline: 1.6671x; 1.6671x over previous
#include <cuda_runtime.h>
#include <cuda_bf16.h>
#include <cstdint>
#include <cstddef>

#define BATCH   2
#define SEQ     4096
#define DMODEL  2048
#define DINNER  4096
#define NHEADS  32
#define DHEAD   128
#define DSTATE  64
#define CONVDIM 4224          // DINNER + 2*DSTATE
#define EPROJ   8352          // 2*DINNER + 2*DSTATE + NHEADS
#define NCHUNK  16
#define CHUNK   256
#define MROWS   8192          // BATCH*SEQ

// ---------------- device scratch (static: allocation-free) ----------------
__device__ float g_zx[(size_t)MROWS * EPROJ];     // in_proj output
__device__ float g_xc[(size_t)MROWS * CONVDIM];   // conv+silu output
__device__ float g_dtv[(size_t)MROWS * NHEADS];   // softplus dt
__device__ float g_cum[BATCH * NCHUNK * NHEADS * CHUNK]; // per-chunk cumsum(dA)
__device__ float g_st[(size_t)BATCH * NCHUNK * NHEADS * DHEAD * DSTATE]; // chunk states
__device__ float g_pv[(size_t)BATCH * NCHUNK * NHEADS * DHEAD * DSTATE]; // prev states
__device__ float g_y [(size_t)MROWS * DINNER];    // y, then yn in place

// ============================================================================
// HMMA bf16x3 NT GEMM: C[M,N] = A[M,K] * B[N,K]^T  (fp32 in/out).
// A,B split into hi/lo bf16 on the fly; D = Ah*Bh + Al*Bh + Ah*Bl (fp32 acc).
// mma.sync.m16n8k16 (base ISA — tcgen05 PTX is rejected by this toolchain's
// compute_103 PTX stage). Tile 128x128, BK=32, 2-stage smem double buffer.
// ============================================================================
#define BK      32
#define TROW    80                       // padded row bytes: 16-aligned, 5 mod 8 -> ldmatrix conflict-free
#define TILE_B  (128 * TROW)             // 10240 B per bf16 tile
#define STAGE_B (4 * TILE_B)             // Ah | Al | Bh | Bl
#define GSMEM   (2 * STAGE_B)            // 81920 B

__device__ __forceinline__ uint32_t smem_u32(const void* p) {
    uint32_t a;
    asm("{ .reg .u64 t; cvta.to.shared.u64 t, %1; cvt.u32.u64 %0, t; }" : "=r"(a) : "l"(p));
    return a;
}
__device__ __forceinline__ void ldm4(uint32_t* r, uint32_t a) {
    asm volatile("ldmatrix.sync.aligned.m8n8.x4.shared.b16 {%0,%1,%2,%3}, [%4];"
                 : "=r"(r[0]), "=r"(r[1]), "=r"(r[2]), "=r"(r[3]) : "r"(a));
}
__device__ __forceinline__ void mma16816(float* d, const uint32_t* a, uint32_t b0, uint32_t b1) {
    asm volatile("mma.sync.aligned.m16n8k16.row.col.f32.bf16.bf16.f32 "
                 "{%0,%1,%2,%3}, {%4,%5,%6,%7}, {%8,%9}, {%0,%1,%2,%3};"
                 : "+f"(d[0]), "+f"(d[1]), "+f"(d[2]), "+f"(d[3])
                 : "r"(a[0]), "r"(a[1]), "r"(a[2]), "r"(a[3]), "r"(b0), "r"(b1));
}
__device__ __forceinline__ uint32_t pk2(__nv_bfloat16 a, __nv_bfloat16 b) {
    return (uint32_t)__bfloat16_as_ushort(a) | ((uint32_t)__bfloat16_as_ushort(b) << 16);
}
__device__ __forceinline__ void dec4(float4 v, uint2& h, uint2& l) {
    __nv_bfloat16 h0 = __float2bfloat16_rn(v.x), h1 = __float2bfloat16_rn(v.y);
    __nv_bfloat16 h2 = __float2bfloat16_rn(v.z), h3 = __float2bfloat16_rn(v.w);
    __nv_bfloat16 l0 = __float2bfloat16_rn(v.x - __bfloat162float(h0));
    __nv_bfloat16 l1 = __float2bfloat16_rn(v.y - __bfloat162float(h1));
    __nv_bfloat16 l2 = __float2bfloat16_rn(v.z - __bfloat162float(h2));
    __nv_bfloat16 l3 = __float2bfloat16_rn(v.w - __bfloat162float(h3));
    h = make_uint2(pk2(h0, h1), pk2(h2, h3));
    l = make_uint2(pk2(l0, l1), pk2(l2, l3));
}

// prefetch one 128xBK fp32 chunk of A and B into registers (4 float4 each)
__device__ __forceinline__ void loadreg(float4* pA, float4* pB,
        const float* __restrict__ A, const float* __restrict__ B,
        int m0, int n0, int K, int N, int k0, int t) {
    int row = t >> 3, c = t & 7;
    #pragma unroll
    for (int j = 0; j < 4; j++) {
        int r = row + j * 32;
        pA[j] = *(const float4*)(A + (size_t)(m0 + r) * K + k0 + c * 4);
        if (n0 + r < N)
            pB[j] = *(const float4*)(B + (size_t)(n0 + r) * K + k0 + c * 4);
        else
            pB[j] = make_float4(0.f, 0.f, 0.f, 0.f);
    }
}
// split + store into one smem stage (Ah | Al | Bh | Bl)
__device__ __forceinline__ void st_stage(char* stage, const float4* pA, const float4* pB, int t) {
    int row = t >> 3, c = t & 7;
    #pragma unroll
    for (int j = 0; j < 4; j++) {
        int r = row + j * 32;
        uint32_t off = (uint32_t)r * TROW + c * 8;
        uint2 h, l;
        dec4(pA[j], h, l);
        *(uint2*)(stage + off) = h;
        *(uint2*)(stage + TILE_B + off) = l;
        dec4(pB[j], h, l);
        *(uint2*)(stage + 2 * TILE_B + off) = h;
        *(uint2*)(stage + 3 * TILE_B + off) = l;
    }
}

__global__ __launch_bounds__(256, 1)
void gemm_tc(const float* __restrict__ A, const float* __restrict__ B,
             float* __restrict__ C, int M, int N, int K) {
    extern __shared__ char smem[];
    const uint32_t sb = smem_u32(smem);
    const int t = threadIdx.x, wid = t >> 5, lane = t & 31;
    const int m0 = blockIdx.y * 128, n0b = blockIdx.x * 128;
    const int wm = (wid & 1) * 64, wn = (wid >> 1) * 32;

    float acc[4][4][4];
    #pragma unroll
    for (int i = 0; i < 4; i++)
        #pragma unroll
        for (int j = 0; j < 4; j++)
            #pragma unroll
            for (int k = 0; k < 4; k++) acc[i][j][k] = 0.f;

    const int NC = K / BK;
    float4 pA[4], pB[4];
    loadreg(pA, pB, A, B, m0, n0b, K, N, 0, t);
    st_stage(smem, pA, pB, t);
    __syncthreads();

    const int lr = lane & 15, lh = lane >> 4;

    for (int c = 0; c < NC; c++) {
        if (c + 1 < NC)
            loadreg(pA, pB, A, B, m0, n0b, K, N, (c + 1) * BK, t);
        uint32_t stb = sb + (uint32_t)(c & 1) * STAGE_B;
        #pragma unroll
        for (int kk = 0; kk < 2; kk++) {
            uint32_t kb = kk * 32 + lh * 16;
            uint32_t ah[4][4], al[4][4], bh[2][4], bl[2][4];
            #pragma unroll
            for (int mf = 0; mf < 4; mf++) {
                uint32_t ro = (uint32_t)(wm + mf * 16 + lr) * TROW + kb;
                ldm4(ah[mf], stb + ro);
                ldm4(al[mf], stb + TILE_B + ro);
            }
            #pragma unroll
            for (int np = 0; np < 2; np++) {
                uint32_t ro = (uint32_t)(wn + np * 16 + lr) * TROW + kb;
                ldm4(bh[np], stb + 2 * TILE_B + ro);
                ldm4(bl[np], stb + 3 * TILE_B + ro);
            }
            #pragma unroll
            for (int mf = 0; mf < 4; mf++)
                #pragma unroll
                for (int np = 0; np < 2; np++) {
                    mma16816(acc[mf][2 * np],     ah[mf], bh[np][0], bh[np][2]);
                    mma16816(acc[mf][2 * np + 1], ah[mf], bh[np][1], bh[np][3]);
                    mma16816(acc[mf][2 * np],     al[mf], bh[np][0], bh[np][2]);
                    mma16816(acc[mf][2 * np + 1], al[mf], bh[np][1], bh[np][3]);
                    mma16816(acc[mf][2 * np],     ah[mf], bl[np][0], bl[np][2]);
                    mma16816(acc[mf][2 * np + 1], ah[mf], bl[np][1], bl[np][3]);
                }
        }
        __syncthreads();
        if (c + 1 < NC) {
            st_stage(smem + ((c + 1) & 1) * STAGE_B, pA, pB, t);
            __syncthreads();
        }
    }

    // epilogue: mma C layout — row = lane>>2 (+8), col = (lane&3)*2 (+1)
    const int gr = lane >> 2, gc = (lane & 3) * 2;
    #pragma unroll
    for (int mf = 0; mf < 4; mf++) {
        int m = m0 + wm + mf * 16 + gr;
        #pragma unroll
        for (int nf = 0; nf < 4; nf++) {
            int n = n0b + wn + nf * 8 + gc;
            if (n < N) {
                *(float2*)&C[(size_t)m * N + n] =
                    make_float2(acc[mf][nf][0], acc[mf][nf][1]);
                *(float2*)&C[(size_t)(m + 8) * N + n] =
                    make_float2(acc[mf][nf][2], acc[mf][nf][3]);
            }
        }
    }
}

// ---------------- conv1d (depthwise, causal, D_CONV=4) + SiLU ----------------
__global__ void conv_silu_k(const float* __restrict__ cw, const float* __restrict__ cb) {
    size_t idx = (size_t)blockIdx.x * 256 + threadIdx.x;
    int c = (int)(idx % CONVDIM);
    size_t bl = idx / CONVDIM;
    int l = (int)(bl % SEQ);
    int b = (int)(bl / SEQ);
    float acc = cb[c];
    #pragma unroll
    for (int k = 0; k < 4; k++) {
        int ls = l - 3 + k;
        if (ls >= 0)
            acc += g_zx[((size_t)(b * SEQ + ls)) * EPROJ + DINNER + c] * cw[c * 4 + k];
    }
    acc = acc / (1.f + expf(-acc));
    g_xc[idx] = acc;
}

// ---------------- dt softplus + per-chunk cumsum(dA) ----------------
__global__ void dtcum_k(const float* __restrict__ dtb, const float* __restrict__ Alog) {
    int blk = blockIdx.x;                // ((b*16+c)*32+h)
    int h = blk & 31, c = (blk >> 5) & 15, b = blk >> 9;
    int s = threadIdx.x;
    int l = c * CHUNK + s;
    float raw = g_zx[((size_t)(b * SEQ + l)) * EPROJ + (EPROJ - NHEADS) + h] + dtb[h];
    float dtv = (raw > 20.f) ? raw : log1pf(expf(raw));
    g_dtv[(size_t)(b * SEQ + l) * NHEADS + h] = dtv;
    float dA = dtv * (-expf(Alog[h]));
    __shared__ float sc[256];
    sc[s] = dA;
    __syncthreads();
    for (int off = 1; off < 256; off <<= 1) {
        float v = (s >= off) ? sc[s - off] : 0.f;
        __syncthreads();
        sc[s] += v;
        __syncthreads();
    }
    g_cum[blk * CHUNK + s] = sc[s];
}

// ---------------- per-chunk states: st[p,n] = sum_z exp(cumL-cum[z])*dt[z]*x[z,p]*B[z,n]
__global__ __launch_bounds__(256)
void states_k() {
    extern __shared__ float sm[];
    float* xw  = sm;                 // 64*128
    float* Bsh = xw + 64 * 128;      // 64*64
    float* ws  = Bsh + 64 * 64;      // 256
    int blk = blockIdx.x;
    int h = blk & 31, c = (blk >> 5) & 15, b = blk >> 9;
    int t = threadIdx.x;
    float clast = g_cum[blk * CHUNK + 255];
    {
        float cz = g_cum[blk * CHUNK + t];
        float dtv = g_dtv[(size_t)(b * SEQ + c * CHUNK + t) * NHEADS + h];
        ws[t] = expf(clast - cz) * dtv;
    }
    __syncthreads();
    int tx = t & 15, ty = t >> 4;
    int p0 = tx * 8, n0 = ty * 4;
    float acc[8][4];
    #pragma unroll
    for (int i = 0; i < 8; i++)
        #pragma unroll
        for (int j = 0; j < 4; j++) acc[i][j] = 0.f;
    size_t base = (size_t)(b * SEQ + c * CHUNK) * CONVDIM;
    for (int zt = 0; zt < 4; zt++) {
        #pragma unroll
        for (int i = 0; i < 32; i++) {
            int lin = t + i * 256; int zz = lin >> 7; int p = lin & 127; int z = zt * 64 + zz;
            xw[zz * 128 + p] = g_xc[base + (size_t)z * CONVDIM + h * DHEAD + p] * ws[z];
        }
        #pragma unroll
        for (int i = 0; i < 16; i++) {
            int lin = t + i * 256; int zz = lin >> 6; int n = lin & 63; int z = zt * 64 + zz;
            Bsh[zz * 64 + n] = g_xc[base + (size_t)z * CONVDIM + DINNER + n];
        }
        __syncthreads();
        #pragma unroll
        for (int zz = 0; zz < 64; zz++) {
            float xv[8];
            *(float4*)&xv[0] = *(const float4*)&xw[zz * 128 + p0];
            *(float4*)&xv[4] = *(const float4*)&xw[zz * 128 + p0 + 4];
            float4 bv = *(const float4*)&Bsh[zz * 64 + n0];
            float bb[4] = {bv.x, bv.y, bv.z, bv.w};
            #pragma unroll
            for (int i = 0; i < 8; i++)
                #pragma unroll
                for (int j = 0; j < 4; j++)
                    acc[i][j] += xv[i] * bb[j];
        }
        __syncthreads();
    }
    size_t ob = (size_t)blk * DHEAD * DSTATE;
    #pragma unroll
    for (int i = 0; i < 8; i++)
        #pragma unroll
        for (int j = 0; j < 4; j++)
            g_st[ob + (size_t)(p0 + i) * DSTATE + n0 + j] = acc[i][j];
}

// ---------------- inter-chunk scan (16 steps, parallel over (b,h) and (p,n))
__global__ void scan_k() {
    int blk = blockIdx.x;                // b*32 + h
    int h = blk & 31, b = blk >> 5;
    int t = threadIdx.x;
    float carry[32];
    #pragma unroll
    for (int k = 0; k < 32; k++) carry[k] = 0.f;
    for (int c = 0; c < NCHUNK; c++) {
        int idx = (b * NCHUNK + c) * NHEADS + h;
        float decay = expf(g_cum[idx * CHUNK + 255]);
        size_t base = (size_t)idx * DHEAD * DSTATE;
        #pragma unroll
        for (int k = 0; k < 32; k++) {
            size_t e = base + t + k * 256;
            g_pv[e] = carry[k];
            carry[k] = carry[k] * decay + g_st[e];
        }
    }
}

// ---------------- Y kernel: Y = masked(C B^T L) @ xdt + exp(cum)*C@prev^T + D*x
#define BTS 260
#define CTS 68
#define PTS 132
__global__ __launch_bounds__(256, 1)
void y_k(const float* __restrict__ Dvec) {
    extern __shared__ float sm[];
    float* Bt   = sm;                  // [64][BTS]  B^T (n-major)
    float* Gtt  = Bt + 64 * BTS;       // [256][64]  G^T (z-major, masked*L)
    float* Ct   = Gtt + 256 * 64;      // [64][CTS]  C^T tile (n-major)
    float* sX   = Ct + 64 * CTS;       // [64][128]  xdt z-tile
    float* pT   = sX + 64 * 128;       // [64][PTS]  prev^T (n-major)
    float* cums = pT + 64 * PTS;       // [256]
    float* sdt  = cums + 256;          // [256]
    int blk = blockIdx.x;
    int h = blk & 31, c = (blk >> 5) & 15, b = blk >> 9;
    int t = threadIdx.x;
    size_t base = (size_t)(b * SEQ + c * CHUNK) * CONVDIM;

    cums[t] = g_cum[blk * CHUNK + t];
    sdt[t]  = g_dtv[(size_t)(b * SEQ + c * CHUNK + t) * NHEADS + h];
    #pragma unroll
    for (int i = 0; i < 64; i++) {
        int lin = t + i * 256; int n = lin & 63; int z = lin >> 6;
        Bt[n * BTS + z] = g_xc[base + (size_t)z * CONVDIM + DINNER + n];
    }
    size_t pvb = (size_t)blk * DHEAD * DSTATE;
    #pragma unroll
    for (int i = 0; i < 32; i++) {
        int lin = t + i * 256; int n = lin & 63; int p = lin >> 6;
        pT[n * PTS + p] = g_pv[pvb + (size_t)p * DSTATE + n];
    }
    __syncthreads();
    float Dh = Dvec[h];
    const int sg = t & 15, zg = t >> 4;    // phase-1 mapping
    const int pg = t & 15, sg2 = t >> 4;   // phase-2/3 mapping

    for (int st = 0; st < 4; st++) {
        int s0 = st * 64;
        #pragma unroll
        for (int i = 0; i < 16; i++) {
            int lin = t + i * 256; int n = lin & 63; int si = lin >> 6;
            Ct[n * CTS + si] = g_xc[base + (size_t)(s0 + si) * CONVDIM + DINNER + DSTATE + n];
        }
        __syncthreads();
        // -------- phase 1: G^T tile = (C_tile · B^T), masked * L --------
        {
            int sl0 = sg * 4, z0 = zg * 16;
            float acc1[4][16];
            #pragma unroll
            for (int i = 0; i < 4; i++)
                #pragma unroll
                for (int j = 0; j < 16; j++) acc1[i][j] = 0.f;
            if (z0 <= s0 + 63) {
                for (int n = 0; n < 64; n++) {
                    float cv[4];
                    *(float4*)cv = *(const float4*)&Ct[n * CTS + sl0];
                    float bz[16];
                    #pragma unroll
                    for (int j = 0; j < 16; j += 4)
                        *(float4*)&bz[j] = *(const float4*)&Bt[n * BTS + z0 + j];
                    #pragma unroll
                    for (int i = 0; i < 4; i++)
                        #pragma unroll
                        for (int j = 0; j < 16; j++)
                            acc1[i][j] += cv[i] * bz[j];
                }
            }
            #pragma unroll
            for (int i = 0; i < 4; i++) {
                int sgl = s0 + sl0 + i;
                float cs = cums[sgl];
                #pragma unroll
                for (int j = 0; j < 16; j++) {
                    int z = z0 + j;
                    float v = (z <= sgl) ? acc1[i][j] * expf(cs - cums[z]) : 0.f;
                    Gtt[z * 64 + sl0 + i] = v;
                }
            }
        }
        __syncthreads();
        // -------- phase 2: Y_tile += G^T-masked @ xdt (skip fully-masked z-tiles)
        int p0 = pg * 8, sl0 = sg2 * 4;
        float acc2[4][8];
        #pragma unroll
        for (int i = 0; i < 4; i++)
            #pragma unroll
            for (int j = 0; j < 8; j++) acc2[i][j] = 0.f;
        for (int zt = 0; zt <= st; zt++) {
            #pragma unroll
            for (int i = 0; i < 32; i++) {
                int lin = t + i * 256; int zz = lin >> 7; int p = lin & 127; int z = zt * 64 + zz;
                sX[zz * 128 + p] = g_xc[base + (size_t)z * CONVDIM + h * DHEAD + p] * sdt[z];
            }
            __syncthreads();
            #pragma unroll
            for (int zz = 0; zz < 64; zz++) {
                float gv[4];
                *(float4*)gv = *(const float4*)&Gtt[(zt * 64 + zz) * 64 + sl0];
                float xv[8];
                *(float4*)&xv[0] = *(const float4*)&sX[zz * 128 + p0];
                *(float4*)&xv[4] = *(const float4*)&sX[zz * 128 + p0 + 4];
                #pragma unroll
                for (int i = 0; i < 4; i++)
                    #pragma unroll
                    for (int j = 0; j < 8; j++)
                        acc2[i][j] += gv[i] * xv[j];
            }
            __syncthreads();
        }
        // -------- phase 3: Y_off = exp(cum[s]) * C · prev^T --------
        {
            float es[4];
            #pragma unroll
            for (int i = 0; i < 4; i++) es[i] = expf(cums[s0 + sl0 + i]);
            for (int n = 0; n < 64; n++) {
                float cv[4];
                *(float4*)cv = *(const float4*)&Ct[n * CTS + sl0];
                float pv[8];
                *(float4*)&pv[0] = *(const float4*)&pT[n * PTS + p0];
                *(float4*)&pv[4] = *(const float4*)&pT[n * PTS + p0 + 4];
                #pragma unroll
                for (int i = 0; i < 4; i++) {
                    float cvs = cv[i] * es[i];
                    #pragma unroll
                    for (int j = 0; j < 8; j++)
                        acc2[i][j] += cvs * pv[j];
                }
            }
        }
        // -------- store: + D*x --------
        #pragma unroll
        for (int i = 0; i < 4; i++) {
            int s = s0 + sl0 + i;
            size_t row = (size_t)(b * SEQ + c * CHUNK + s);
            #pragma unroll
            for (int j = 0; j < 8; j++) {
                int p = p0 + j;
                g_y[row * DINNER + h * DHEAD + p] =
                    acc2[i][j] + Dh * g_xc[row * CONVDIM + h * DHEAD + p];
            }
        }
        __syncthreads();
    }
}

// ---------------- gated RMSNorm (in place on g_y) ----------------
__global__ void gatenorm_k(const float* __restrict__ nw) {
    int row = blockIdx.x;
    __shared__ float yg[DINNER];
    __shared__ float red[256];
    int t = threadIdx.x;
    float ss = 0.f;
    size_t zb = (size_t)row * EPROJ;
    size_t yb = (size_t)row * DINNER;
    #pragma unroll
    for (int i = 0; i < 16; i++) {
        int e = t + i * 256;
        float z = g_zx[zb + e];
        float sz = z / (1.f + expf(-z));
        float v = g_y[yb + e] * sz;
        yg[e] = v;
        ss += v * v;
    }
    red[t] = ss;
    __syncthreads();
    for (int off = 128; off > 0; off >>= 1) {
        if (t < off) red[t] += red[t + off];
        __syncthreads();
    }
    float scale = rsqrtf(red[0] / (float)DINNER + 1e-5f);
    #pragma unroll
    for (int i = 0; i < 16; i++) {
        int e = t + i * 256;
        g_y[yb + e] = yg[e] * scale * nw[e];
    }
}

// ---------------- launch ----------------
extern "C" void kernel_launch(void* const* d_in, const int* in_sizes, int n_in,
                              void* d_out, int out_size) {
    const float* u     = (const float*)d_in[0];
    const float* W_in  = (const float*)d_in[1];
    const float* convw = (const float*)d_in[2];
    const float* convb = (const float*)d_in[3];
    const float* dtb   = (const float*)d_in[4];
    const float* Alog  = (const float*)d_in[5];
    const float* Dvec  = (const float*)d_in[6];
    const float* nw    = (const float*)d_in[7];
    const float* W_out = (const float*)d_in[8];
    float* out = (float*)d_out;

    float *zx_p, *y_p;
    cudaGetSymbolAddress((void**)&zx_p, g_zx);
    cudaGetSymbolAddress((void**)&y_p,  g_y);

    const int STATES_SMEM = (64 * 128 + 64 * 64 + 256) * 4;
    const int Y_SMEM = (64 * BTS + 256 * 64 + 64 * CTS + 64 * 128 + 64 * PTS + 512) * 4;
    cudaFuncSetAttribute(states_k, cudaFuncAttributeMaxDynamicSharedMemorySize, STATES_SMEM);
    cudaFuncSetAttribute(y_k,      cudaFuncAttributeMaxDynamicSharedMemorySize, Y_SMEM);
    cudaFuncSetAttribute(gemm_tc,  cudaFuncAttributeMaxDynamicSharedMemorySize, GSMEM);

    // 1. in_proj GEMM: [8192,8352] = u[8192,2048] @ W_in[8352,2048]^T  (HMMA bf16x3)
    gemm_tc<<<dim3(66, 64), 256, GSMEM>>>(u, W_in, zx_p, MROWS, EPROJ, DMODEL);
    // 2. causal depthwise conv + SiLU
    conv_silu_k<<<(int)(((size_t)MROWS * CONVDIM) / 256), 256>>>(convw, convb);
    // 3. dt softplus + per-chunk cumsum(dA)
    dtcum_k<<<1024, 256>>>(dtb, Alog);
    // 4. per-chunk states
    states_k<<<1024, 256, STATES_SMEM>>>();
    // 5. inter-chunk scan
    scan_k<<<64, 256>>>();
    // 6. Y = diag + off + D*x
    y_k<<<1024, 256, Y_SMEM>>>(Dvec);
    // 7. gated RMSNorm
    gatenorm_k<<<MROWS, 256>>>(nw);
    // 8. out_proj GEMM: [8192,2048] = yn[8192,4096] @ W_out[2048,4096]^T  (HMMA bf16x3)
    gemm_tc<<<dim3(16, 64), 256, GSMEM>>>(y_p, W_out, out, MROWS, DMODEL, DINNER);
}

// round 7
// speedup vs baseline: 1.8341x; 1.1002x over previous
#include <cuda_runtime.h>
#include <cuda_bf16.h>
#include <cstdint>
#include <cstddef>

#define BATCH   2
#define SEQ     4096
#define DMODEL  2048
#define DINNER  4096
#define NHEADS  32
#define DHEAD   128
#define DSTATE  64
#define CONVDIM 4224          // DINNER + 2*DSTATE
#define EPROJ   8352          // 2*DINNER + 2*DSTATE + NHEADS
#define NCHUNK  16
#define CHUNK   256
#define MROWS   8192          // BATCH*SEQ

// ---------------- device scratch (static: allocation-free) ----------------
__device__ float g_zx[(size_t)MROWS * EPROJ];     // in_proj output
__device__ float g_xc[(size_t)MROWS * CONVDIM];   // conv+silu output
__device__ float g_dtv[(size_t)MROWS * NHEADS];   // softplus dt
__device__ float g_cum[BATCH * NCHUNK * NHEADS * CHUNK]; // per-chunk cumsum(dA)
__device__ float g_st[(size_t)BATCH * NCHUNK * NHEADS * DHEAD * DSTATE]; // chunk states
__device__ float g_pv[(size_t)BATCH * NCHUNK * NHEADS * DHEAD * DSTATE]; // prev states
__device__ float g_y [(size_t)MROWS * DINNER];    // y, then yn in place
// pre-split bf16 operands (hi/lo); sized for the larger GEMM use
__device__ __nv_bfloat16 g_Ah[(size_t)MROWS * DINNER];
__device__ __nv_bfloat16 g_Al[(size_t)MROWS * DINNER];
__device__ __nv_bfloat16 g_Bh[(size_t)EPROJ * DMODEL];
__device__ __nv_bfloat16 g_Bl[(size_t)EPROJ * DMODEL];

// ============================================================================
// helpers
// ============================================================================
__device__ __forceinline__ uint32_t smem_u32(const void* p) {
    uint32_t a;
    asm("{ .reg .u64 t; cvta.to.shared.u64 t, %1; cvt.u32.u64 %0, t; }" : "=r"(a) : "l"(p));
    return a;
}
__device__ __forceinline__ void ldm4(uint32_t* r, uint32_t a) {
    asm volatile("ldmatrix.sync.aligned.m8n8.x4.shared.b16 {%0,%1,%2,%3}, [%4];"
                 : "=r"(r[0]), "=r"(r[1]), "=r"(r[2]), "=r"(r[3]) : "r"(a));
}
__device__ __forceinline__ void mma16816(float* d, const uint32_t* a, uint32_t b0, uint32_t b1) {
    asm volatile("mma.sync.aligned.m16n8k16.row.col.f32.bf16.bf16.f32 "
                 "{%0,%1,%2,%3}, {%4,%5,%6,%7}, {%8,%9}, {%0,%1,%2,%3};"
                 : "+f"(d[0]), "+f"(d[1]), "+f"(d[2]), "+f"(d[3])
                 : "r"(a[0]), "r"(a[1]), "r"(a[2]), "r"(a[3]), "r"(b0), "r"(b1));
}
__device__ __forceinline__ uint32_t pk2(__nv_bfloat16 a, __nv_bfloat16 b) {
    return (uint32_t)__bfloat16_as_ushort(a) | ((uint32_t)__bfloat16_as_ushort(b) << 16);
}
__device__ __forceinline__ void dec4(float4 v, uint2& h, uint2& l) {
    __nv_bfloat16 h0 = __float2bfloat16_rn(v.x), h1 = __float2bfloat16_rn(v.y);
    __nv_bfloat16 h2 = __float2bfloat16_rn(v.z), h3 = __float2bfloat16_rn(v.w);
    __nv_bfloat16 l0 = __float2bfloat16_rn(v.x - __bfloat162float(h0));
    __nv_bfloat16 l1 = __float2bfloat16_rn(v.y - __bfloat162float(h1));
    __nv_bfloat16 l2 = __float2bfloat16_rn(v.z - __bfloat162float(h2));
    __nv_bfloat16 l3 = __float2bfloat16_rn(v.w - __bfloat162float(h3));
    h = make_uint2(pk2(h0, h1), pk2(h2, h3));
    l = make_uint2(pk2(l0, l1), pk2(l2, l3));
}
__device__ __forceinline__ void cpasync16(uint32_t dst, const void* src, int srcsz) {
    asm volatile("cp.async.cg.shared.global [%0], [%1], 16, %2;"
                 :: "r"(dst), "l"(src), "r"(srcsz) : "memory");
}
#define CP_COMMIT() asm volatile("cp.async.commit_group;" ::: "memory")
#define CP_WAIT2()  asm volatile("cp.async.wait_group 2;" ::: "memory")

// ---------------- fp32 -> (hi, lo) bf16 split (memory-bound pass) ----------
__global__ void split_k(const float4* __restrict__ in,
                        uint2* __restrict__ hi, uint2* __restrict__ lo, int n4) {
    int i = blockIdx.x * 256 + threadIdx.x;
    if (i < n4) {
        uint2 h, l;
        dec4(in[i], h, l);
        hi[i] = h;
        lo[i] = l;
    }
}

// ============================================================================
// HMMA bf16x3 NT GEMM on pre-split operands:
// C[M,N] = (Ah+Al)[M,K] * (Bh+Bl)[N,K]^T, D = Ah*Bh + Al*Bh + Ah*Bl.
// Tile 128x128, BK=32, 4-stage cp.async pipeline. Hot loop: cp.async/LDSM/MMA only.
// ============================================================================
#define BK      32
#define TROW    80                       // padded row bytes: 16-aligned, 5 mod 8 -> ldmatrix conflict-free
#define TILE_B  (128 * TROW)             // 10240 B per bf16 tile
#define STAGE_B (4 * TILE_B)             // Ah | Al | Bh | Bl = 40960 B
#define NSTAGE  4
#define GSMEM   (NSTAGE * STAGE_B)       // 163840 B

__device__ __forceinline__ void ld_stage(uint32_t sb, int stage,
        const __nv_bfloat16* __restrict__ Ah, const __nv_bfloat16* __restrict__ Al,
        const __nv_bfloat16* __restrict__ Bh, const __nv_bfloat16* __restrict__ Bl,
        int m0, int n0, int K, int N, int k0, int t) {
    uint32_t stb = sb + (uint32_t)stage * STAGE_B;
    #pragma unroll
    for (int j = 0; j < 8; j++) {
        int lin = t + j * 256;
        int tile = lin >> 9, li = lin & 511;
        int row = li >> 2, c = li & 3;
        uint32_t dst = stb + (uint32_t)tile * TILE_B + (uint32_t)row * TROW + c * 16;
        const __nv_bfloat16* src;
        int sz = 16;
        if (tile == 0)      src = Ah + (size_t)(m0 + row) * K + k0 + c * 8;
        else if (tile == 1) src = Al + (size_t)(m0 + row) * K + k0 + c * 8;
        else {
            const __nv_bfloat16* base = (tile == 2) ? Bh : Bl;
            int r = n0 + row;
            if (r >= N) { r = 0; sz = 0; }
            src = base + (size_t)r * K + k0 + c * 8;
        }
        cpasync16(dst, src, sz);
    }
}

__global__ __launch_bounds__(256, 1)
void gemm_bf(const __nv_bfloat16* __restrict__ Ah, const __nv_bfloat16* __restrict__ Al,
             const __nv_bfloat16* __restrict__ Bh, const __nv_bfloat16* __restrict__ Bl,
             float* __restrict__ C, int M, int N, int K) {
    extern __shared__ char smem[];
    const uint32_t sb = smem_u32(smem);
    const int t = threadIdx.x, wid = t >> 5, lane = t & 31;
    const int m0 = blockIdx.y * 128, n0b = blockIdx.x * 128;
    const int wm = (wid & 1) * 64, wn = (wid >> 1) * 32;

    float acc[4][4][4];
    #pragma unroll
    for (int i = 0; i < 4; i++)
        #pragma unroll
        for (int j = 0; j < 4; j++)
            #pragma unroll
            for (int k = 0; k < 4; k++) acc[i][j][k] = 0.f;

    const int NC = K / BK;
    // prologue: fill 3 stages
    #pragma unroll
    for (int s = 0; s < NSTAGE - 1; s++) {
        if (s < NC)
            ld_stage(sb, s, Ah, Al, Bh, Bl, m0, n0b, K, N, s * BK, t);
        CP_COMMIT();
    }

    const int lr = lane & 15, lh = lane >> 4;

    for (int c = 0; c < NC; c++) {
        CP_WAIT2();
        __syncthreads();
        uint32_t stb = sb + (uint32_t)(c & (NSTAGE - 1)) * STAGE_B;
        #pragma unroll
        for (int kk = 0; kk < 2; kk++) {
            uint32_t kb = kk * 32 + lh * 16;
            uint32_t ah[4][4], al[4][4], bh[2][4], bl[2][4];
            #pragma unroll
            for (int mf = 0; mf < 4; mf++) {
                uint32_t ro = (uint32_t)(wm + mf * 16 + lr) * TROW + kb;
                ldm4(ah[mf], stb + ro);
                ldm4(al[mf], stb + TILE_B + ro);
            }
            #pragma unroll
            for (int np = 0; np < 2; np++) {
                uint32_t ro = (uint32_t)(wn + np * 16 + lr) * TROW + kb;
                ldm4(bh[np], stb + 2 * TILE_B + ro);
                ldm4(bl[np], stb + 3 * TILE_B + ro);
            }
            #pragma unroll
            for (int mf = 0; mf < 4; mf++)
                #pragma unroll
                for (int np = 0; np < 2; np++) {
                    mma16816(acc[mf][2 * np],     ah[mf], bh[np][0], bh[np][2]);
                    mma16816(acc[mf][2 * np + 1], ah[mf], bh[np][1], bh[np][3]);
                    mma16816(acc[mf][2 * np],     al[mf], bh[np][0], bh[np][2]);
                    mma16816(acc[mf][2 * np + 1], al[mf], bh[np][1], bh[np][3]);
                    mma16816(acc[mf][2 * np],     ah[mf], bl[np][0], bl[np][2]);
                    mma16816(acc[mf][2 * np + 1], ah[mf], bl[np][1], bl[np][3]);
                }
        }
        __syncthreads();
        int nx = c + NSTAGE - 1;
        if (nx < NC)
            ld_stage(sb, nx & (NSTAGE - 1), Ah, Al, Bh, Bl, m0, n0b, K, N, nx * BK, t);
        CP_COMMIT();
    }

    // epilogue: mma C layout — row = lane>>2 (+8), col = (lane&3)*2 (+1)
    const int gr = lane >> 2, gc = (lane & 3) * 2;
    #pragma unroll
    for (int mf = 0; mf < 4; mf++) {
        int m = m0 + wm + mf * 16 + gr;
        #pragma unroll
        for (int nf = 0; nf < 4; nf++) {
            int n = n0b + wn + nf * 8 + gc;
            if (n < N) {
                *(float2*)&C[(size_t)m * N + n] =
                    make_float2(acc[mf][nf][0], acc[mf][nf][1]);
                *(float2*)&C[(size_t)(m + 8) * N + n] =
                    make_float2(acc[mf][nf][2], acc[mf][nf][3]);
            }
        }
    }
}

// ---------------- conv1d (depthwise, causal, D_CONV=4) + SiLU ----------------
__global__ void conv_silu_k(const float* __restrict__ cw, const float* __restrict__ cb) {
    size_t idx = (size_t)blockIdx.x * 256 + threadIdx.x;
    int c = (int)(idx % CONVDIM);
    size_t bl = idx / CONVDIM;
    int l = (int)(bl % SEQ);
    int b = (int)(bl / SEQ);
    float acc = cb[c];
    #pragma unroll
    for (int k = 0; k < 4; k++) {
        int ls = l - 3 + k;
        if (ls >= 0)
            acc += g_zx[((size_t)(b * SEQ + ls)) * EPROJ + DINNER + c] * cw[c * 4 + k];
    }
    acc = acc / (1.f + expf(-acc));
    g_xc[idx] = acc;
}

// ---------------- dt softplus + per-chunk cumsum(dA) ----------------
__global__ void dtcum_k(const float* __restrict__ dtb, const float* __restrict__ Alog) {
    int blk = blockIdx.x;                // ((b*16+c)*32+h)
    int h = blk & 31, c = (blk >> 5) & 15, b = blk >> 9;
    int s = threadIdx.x;
    int l = c * CHUNK + s;
    float raw = g_zx[((size_t)(b * SEQ + l)) * EPROJ + (EPROJ - NHEADS) + h] + dtb[h];
    float dtv = (raw > 20.f) ? raw : log1pf(expf(raw));
    g_dtv[(size_t)(b * SEQ + l) * NHEADS + h] = dtv;
    float dA = dtv * (-expf(Alog[h]));
    __shared__ float sc[256];
    sc[s] = dA;
    __syncthreads();
    for (int off = 1; off < 256; off <<= 1) {
        float v = (s >= off) ? sc[s - off] : 0.f;
        __syncthreads();
        sc[s] += v;
        __syncthreads();
    }
    g_cum[blk * CHUNK + s] = sc[s];
}

// ---------------- per-chunk states: st[p,n] = sum_z exp(cumL-cum[z])*dt[z]*x[z,p]*B[z,n]
__global__ __launch_bounds__(256)
void states_k() {
    extern __shared__ float sm[];
    float* xw  = sm;                 // 64*128
    float* Bsh = xw + 64 * 128;      // 64*64
    float* ws  = Bsh + 64 * 64;      // 256
    int blk = blockIdx.x;
    int h = blk & 31, c = (blk >> 5) & 15, b = blk >> 9;
    int t = threadIdx.x;
    float clast = g_cum[blk * CHUNK + 255];
    {
        float cz = g_cum[blk * CHUNK + t];
        float dtv = g_dtv[(size_t)(b * SEQ + c * CHUNK + t) * NHEADS + h];
        ws[t] = expf(clast - cz) * dtv;
    }
    __syncthreads();
    int tx = t & 15, ty = t >> 4;
    int p0 = tx * 8, n0 = ty * 4;
    float acc[8][4];
    #pragma unroll
    for (int i = 0; i < 8; i++)
        #pragma unroll
        for (int j = 0; j < 4; j++) acc[i][j] = 0.f;
    size_t base = (size_t)(b * SEQ + c * CHUNK) * CONVDIM;
    for (int zt = 0; zt < 4; zt++) {
        #pragma unroll
        for (int i = 0; i < 32; i++) {
            int lin = t + i * 256; int zz = lin >> 7; int p = lin & 127; int z = zt * 64 + zz;
            xw[zz * 128 + p] = g_xc[base + (size_t)z * CONVDIM + h * DHEAD + p] * ws[z];
        }
        #pragma unroll
        for (int i = 0; i < 16; i++) {
            int lin = t + i * 256; int zz = lin >> 6; int n = lin & 63; int z = zt * 64 + zz;
            Bsh[zz * 64 + n] = g_xc[base + (size_t)z * CONVDIM + DINNER + n];
        }
        __syncthreads();
        #pragma unroll
        for (int zz = 0; zz < 64; zz++) {
            float xv[8];
            *(float4*)&xv[0] = *(const float4*)&xw[zz * 128 + p0];
            *(float4*)&xv[4] = *(const float4*)&xw[zz * 128 + p0 + 4];
            float4 bv = *(const float4*)&Bsh[zz * 64 + n0];
            float bb[4] = {bv.x, bv.y, bv.z, bv.w};
            #pragma unroll
            for (int i = 0; i < 8; i++)
                #pragma unroll
                for (int j = 0; j < 4; j++)
                    acc[i][j] += xv[i] * bb[j];
        }
        __syncthreads();
    }
    size_t ob = (size_t)blk * DHEAD * DSTATE;
    #pragma unroll
    for (int i = 0; i < 8; i++)
        #pragma unroll
        for (int j = 0; j < 4; j++)
            g_st[ob + (size_t)(p0 + i) * DSTATE + n0 + j] = acc[i][j];
}

// ---------------- inter-chunk scan (16 steps, parallel over (b,h) and (p,n))
__global__ void scan_k() {
    int blk = blockIdx.x;                // b*32 + h
    int h = blk & 31, b = blk >> 5;
    int t = threadIdx.x;
    float carry[32];
    #pragma unroll
    for (int k = 0; k < 32; k++) carry[k] = 0.f;
    for (int c = 0; c < NCHUNK; c++) {
        int idx = (b * NCHUNK + c) * NHEADS + h;
        float decay = expf(g_cum[idx * CHUNK + 255]);
        size_t base = (size_t)idx * DHEAD * DSTATE;
        #pragma unroll
        for (int k = 0; k < 32; k++) {
            size_t e = base + t + k * 256;
            g_pv[e] = carry[k];
            carry[k] = carry[k] * decay + g_st[e];
        }
    }
}

// ---------------- Y kernel: Y = masked(C B^T L) @ xdt + exp(cum)*C@prev^T + D*x
#define BTS 260
#define CTS 68
#define PTS 132
__global__ __launch_bounds__(256, 1)
void y_k(const float* __restrict__ Dvec) {
    extern __shared__ float sm[];
    float* Bt   = sm;                  // [64][BTS]  B^T (n-major)
    float* Gtt  = Bt + 64 * BTS;       // [256][64]  G^T (z-major, masked*L)
    float* Ct   = Gtt + 256 * 64;      // [64][CTS]  C^T tile (n-major)
    float* sX   = Ct + 64 * CTS;       // [64][128]  xdt z-tile
    float* pT   = sX + 64 * 128;       // [64][PTS]  prev^T (n-major)
    float* cums = pT + 64 * PTS;       // [256]
    float* sdt  = cums + 256;          // [256]
    int blk = blockIdx.x;
    int h = blk & 31, c = (blk >> 5) & 15, b = blk >> 9;
    int t = threadIdx.x;
    size_t base = (size_t)(b * SEQ + c * CHUNK) * CONVDIM;

    cums[t] = g_cum[blk * CHUNK + t];
    sdt[t]  = g_dtv[(size_t)(b * SEQ + c * CHUNK + t) * NHEADS + h];
    #pragma unroll
    for (int i = 0; i < 64; i++) {
        int lin = t + i * 256; int n = lin & 63; int z = lin >> 6;
        Bt[n * BTS + z] = g_xc[base + (size_t)z * CONVDIM + DINNER + n];
    }
    size_t pvb = (size_t)blk * DHEAD * DSTATE;
    #pragma unroll
    for (int i = 0; i < 32; i++) {
        int lin = t + i * 256; int n = lin & 63; int p = lin >> 6;
        pT[n * PTS + p] = g_pv[pvb + (size_t)p * DSTATE + n];
    }
    __syncthreads();
    float Dh = Dvec[h];
    const int sg = t & 15, zg = t >> 4;    // phase-1 mapping
    const int pg = t & 15, sg2 = t >> 4;   // phase-2/3 mapping

    for (int st = 0; st < 4; st++) {
        int s0 = st * 64;
        #pragma unroll
        for (int i = 0; i < 16; i++) {
            int lin = t + i * 256; int n = lin & 63; int si = lin >> 6;
            Ct[n * CTS + si] = g_xc[base + (size_t)(s0 + si) * CONVDIM + DINNER + DSTATE + n];
        }
        __syncthreads();
        // -------- phase 1: G^T tile = (C_tile · B^T), masked * L --------
        {
            int sl0 = sg * 4, z0 = zg * 16;
            float acc1[4][16];
            #pragma unroll
            for (int i = 0; i < 4; i++)
                #pragma unroll
                for (int j = 0; j < 16; j++) acc1[i][j] = 0.f;
            if (z0 <= s0 + 63) {
                for (int n = 0; n < 64; n++) {
                    float cv[4];
                    *(float4*)cv = *(const float4*)&Ct[n * CTS + sl0];
                    float bz[16];
                    #pragma unroll
                    for (int j = 0; j < 16; j += 4)
                        *(float4*)&bz[j] = *(const float4*)&Bt[n * BTS + z0 + j];
                    #pragma unroll
                    for (int i = 0; i < 4; i++)
                        #pragma unroll
                        for (int j = 0; j < 16; j++)
                            acc1[i][j] += cv[i] * bz[j];
                }
            }
            #pragma unroll
            for (int i = 0; i < 4; i++) {
                int sgl = s0 + sl0 + i;
                float cs = cums[sgl];
                #pragma unroll
                for (int j = 0; j < 16; j++) {
                    int z = z0 + j;
                    float v = (z <= sgl) ? acc1[i][j] * expf(cs - cums[z]) : 0.f;
                    Gtt[z * 64 + sl0 + i] = v;
                }
            }
        }
        __syncthreads();
        // -------- phase 2: Y_tile += G^T-masked @ xdt (skip fully-masked z-tiles)
        int p0 = pg * 8, sl0 = sg2 * 4;
        float acc2[4][8];
        #pragma unroll
        for (int i = 0; i < 4; i++)
            #pragma unroll
            for (int j = 0; j < 8; j++) acc2[i][j] = 0.f;
        for (int zt = 0; zt <= st; zt++) {
            #pragma unroll
            for (int i = 0; i < 32; i++) {
                int lin = t + i * 256; int zz = lin >> 7; int p = lin & 127; int z = zt * 64 + zz;
                sX[zz * 128 + p] = g_xc[base + (size_t)z * CONVDIM + h * DHEAD + p] * sdt[z];
            }
            __syncthreads();
            #pragma unroll
            for (int zz = 0; zz < 64; zz++) {
                float gv[4];
                *(float4*)gv = *(const float4*)&Gtt[(zt * 64 + zz) * 64 + sl0];
                float xv[8];
                *(float4*)&xv[0] = *(const float4*)&sX[zz * 128 + p0];
                *(float4*)&xv[4] = *(const float4*)&sX[zz * 128 + p0 + 4];
                #pragma unroll
                for (int i = 0; i < 4; i++)
                    #pragma unroll
                    for (int j = 0; j < 8; j++)
                        acc2[i][j] += gv[i] * xv[j];
            }
            __syncthreads();
        }
        // -------- phase 3: Y_off = exp(cum[s]) * C · prev^T --------
        {
            float es[4];
            #pragma unroll
            for (int i = 0; i < 4; i++) es[i] = expf(cums[s0 + sl0 + i]);
            for (int n = 0; n < 64; n++) {
                float cv[4];
                *(float4*)cv = *(const float4*)&Ct[n * CTS + sl0];
                float pv[8];
                *(float4*)&pv[0] = *(const float4*)&pT[n * PTS + p0];
                *(float4*)&pv[4] = *(const float4*)&pT[n * PTS + p0 + 4];
                #pragma unroll
                for (int i = 0; i < 4; i++) {
                    float cvs = cv[i] * es[i];
                    #pragma unroll
                    for (int j = 0; j < 8; j++)
                        acc2[i][j] += cvs * pv[j];
                }
            }
        }
        // -------- store: + D*x --------
        #pragma unroll
        for (int i = 0; i < 4; i++) {
            int s = s0 + sl0 + i;
            size_t row = (size_t)(b * SEQ + c * CHUNK + s);
            #pragma unroll
            for (int j = 0; j < 8; j++) {
                int p = p0 + j;
                g_y[row * DINNER + h * DHEAD + p] =
                    acc2[i][j] + Dh * g_xc[row * CONVDIM + h * DHEAD + p];
            }
        }
        __syncthreads();
    }
}

// ---------------- gated RMSNorm (in place on g_y) ----------------
__global__ void gatenorm_k(const float* __restrict__ nw) {
    int row = blockIdx.x;
    __shared__ float yg[DINNER];
    __shared__ float red[256];
    int t = threadIdx.x;
    float ss = 0.f;
    size_t zb = (size_t)row * EPROJ;
    size_t yb = (size_t)row * DINNER;
    #pragma unroll
    for (int i = 0; i < 16; i++) {
        int e = t + i * 256;
        float z = g_zx[zb + e];
        float sz = z / (1.f + expf(-z));
        float v = g_y[yb + e] * sz;
        yg[e] = v;
        ss += v * v;
    }
    red[t] = ss;
    __syncthreads();
    for (int off = 128; off > 0; off >>= 1) {
        if (t < off) red[t] += red[t + off];
        __syncthreads();
    }
    float scale = rsqrtf(red[0] / (float)DINNER + 1e-5f);
    #pragma unroll
    for (int i = 0; i < 16; i++) {
        int e = t + i * 256;
        g_y[yb + e] = yg[e] * scale * nw[e];
    }
}

// ---------------- launch ----------------
extern "C" void kernel_launch(void* const* d_in, const int* in_sizes, int n_in,
                              void* d_out, int out_size) {
    const float* u     = (const float*)d_in[0];
    const float* W_in  = (const float*)d_in[1];
    const float* convw = (const float*)d_in[2];
    const float* convb = (const float*)d_in[3];
    const float* dtb   = (const float*)d_in[4];
    const float* Alog  = (const float*)d_in[5];
    const float* Dvec  = (const float*)d_in[6];
    const float* nw    = (const float*)d_in[7];
    const float* W_out = (const float*)d_in[8];
    float* out = (float*)d_out;

    float *zx_p, *y_p;
    __nv_bfloat16 *ah_p, *al_p, *bh_p, *bl_p;
    cudaGetSymbolAddress((void**)&zx_p, g_zx);
    cudaGetSymbolAddress((void**)&y_p,  g_y);
    cudaGetSymbolAddress((void**)&ah_p, g_Ah);
    cudaGetSymbolAddress((void**)&al_p, g_Al);
    cudaGetSymbolAddress((void**)&bh_p, g_Bh);
    cudaGetSymbolAddress((void**)&bl_p, g_Bl);

    const int STATES_SMEM = (64 * 128 + 64 * 64 + 256) * 4;
    const int Y_SMEM = (64 * BTS + 256 * 64 + 64 * CTS + 64 * 128 + 64 * PTS + 512) * 4;
    cudaFuncSetAttribute(states_k, cudaFuncAttributeMaxDynamicSharedMemorySize, STATES_SMEM);
    cudaFuncSetAttribute(y_k,      cudaFuncAttributeMaxDynamicSharedMemorySize, Y_SMEM);
    cudaFuncSetAttribute(gemm_bf,  cudaFuncAttributeMaxDynamicSharedMemorySize, GSMEM);

    // ---- GEMM1: zx[8192,8352] = u[8192,2048] @ W_in[8352,2048]^T ----
    {
        int n4a = MROWS * DMODEL / 4;       // u
        int n4b = EPROJ * DMODEL / 4;       // W_in
        split_k<<<(n4a + 255) / 256, 256>>>((const float4*)u, (uint2*)ah_p, (uint2*)al_p, n4a);
        split_k<<<(n4b + 255) / 256, 256>>>((const float4*)W_in, (uint2*)bh_p, (uint2*)bl_p, n4b);
        gemm_bf<<<dim3(66, 64), 256, GSMEM>>>(ah_p, al_p, bh_p, bl_p, zx_p,
                                              MROWS, EPROJ, DMODEL);
    }
    // ---- SSD middle section ----
    conv_silu_k<<<(int)(((size_t)MROWS * CONVDIM) / 256), 256>>>(convw, convb);
    dtcum_k<<<1024, 256>>>(dtb, Alog);
    states_k<<<1024, 256, STATES_SMEM>>>();
    scan_k<<<64, 256>>>();
    y_k<<<1024, 256, Y_SMEM>>>(Dvec);
    gatenorm_k<<<MROWS, 256>>>(nw);
    // ---- GEMM2: out[8192,2048] = yn[8192,4096] @ W_out[2048,4096]^T ----
    {
        int n4a = MROWS * DINNER / 4;       // yn
        int n4b = DMODEL * DINNER / 4;      // W_out
        split_k<<<(n4a + 255) / 256, 256>>>((const float4*)y_p, (uint2*)ah_p, (uint2*)al_p, n4a);
        split_k<<<(n4b + 255) / 256, 256>>>((const float4*)W_out, (uint2*)bh_p, (uint2*)bl_p, n4b);
        gemm_bf<<<dim3(16, 64), 256, GSMEM>>>(ah_p, al_p, bh_p, bl_p, out,
                                              MROWS, DMODEL, DINNER);
    }
}